// round 1
// baseline (speedup 1.0000x reference)
#include <cuda_runtime.h>
#include <math.h>

#define NB 16
#define NS 2048
#define NH 128
#define ND 64

typedef unsigned long long u64;

// ---------------- scratch (device globals; no allocation allowed) ----------------
__device__ float g_pe[NS * NH];                 // 1 MB
__device__ float g_xp[NB * NS * NH];            // 16.8 MB
__device__ float g_Q[NB * NS * ND];             // 8.4 MB
__device__ float g_K[NB * NS * ND];             // 8.4 MB
__device__ float g_wvf[NH];
__device__ float g_u[NB * NS];
__device__ float g_Z[NB * NS];
__device__ float g_w[NB * NS];
__device__ float g_E[(size_t)NB * NS * NS];     // 268 MB: exp(scores)

// ---------------- packed fp32x2 helpers (FFMA2: 2x fp32 FMA rate on sm_103a) ------
__device__ __forceinline__ u64 pack_dup(float a) {
    u64 r; asm("mov.b64 %0, {%1,%1};" : "=l"(r) : "f"(a)); return r;
}
__device__ __forceinline__ u64 pack2(float lo, float hi) {
    u64 r; asm("mov.b64 %0, {%1,%2};" : "=l"(r) : "f"(lo), "f"(hi)); return r;
}
__device__ __forceinline__ void fma2(u64& c, u64 a, u64 b) {
    asm("fma.rn.f32x2 %0, %1, %2, %0;" : "+l"(c) : "l"(a), "l"(b));
}
__device__ __forceinline__ float2 unpack2(u64 v) {
    float lo, hi; asm("mov.b64 {%0,%1}, %2;" : "=f"(lo), "=f"(hi) : "l"(v));
    return make_float2(lo, hi);
}

// ---------------- kernel 1: sinusoidal PE (double precision internals) ------------
__global__ void k_pe() {
    int p = blockIdx.x;
    int i = threadIdx.x;  // 0..63
    double rate = pow(10000.0, (double)(2 * i) / 128.0);
    double ang = (double)p / rate;
    g_pe[p * NH + 2 * i]     = (float)sin(ang);
    g_pe[p * NH + 2 * i + 1] = (float)cos(ang);
}

// ---------------- kernel 2: xp = x + pe (broadcast over batch) --------------------
__global__ void k_xp(const float* __restrict__ x) {
    int idx = blockIdx.x * blockDim.x + threadIdx.x;   // grid covers NB*NS*NH exactly
    g_xp[idx] = x[idx] + g_pe[idx & (NS * NH - 1)];
}

// ---------------- kernel 3: wvf = Wv @ Wf  (fold V and output proj) ---------------
__global__ void k_wvf(const float* __restrict__ Wv, const float* __restrict__ Wf) {
    int h = threadIdx.x;  // 128
    float s = 0.f;
    #pragma unroll 8
    for (int d = 0; d < ND; d++) s += Wv[h * ND + d] * Wf[d];
    g_wvf[h] = s;
}

// ---------------- kernel 4: projections Q = xp@Wq, K = xp@Wk ----------------------
// BM=64 rows x BN=128 cols (Wq|Wk), full depth K=128. 256 threads, FFMA2 inner loop.
__global__ __launch_bounds__(256, 2) void k_proj(const float* __restrict__ Wq,
                                                 const float* __restrict__ Wk) {
    extern __shared__ float sm[];
    float* As = sm;              // [64][128] row-major
    float* Bs = sm + 64 * 128;   // [128][128] (k-major): col<64 -> Wq, else Wk

    int t = threadIdx.x;
    int row0 = blockIdx.x * 64;

    // load weights: 4096 float4
    const float4* Wq4 = (const float4*)Wq;
    const float4* Wk4 = (const float4*)Wk;
    float4* Bs4 = (float4*)Bs;
    #pragma unroll
    for (int i = 0; i < 16; i++) {
        int e = t + i * 256;           // float4 index over [128][32]
        int k = e >> 5, n4 = e & 31;
        Bs4[e] = (n4 < 16) ? Wq4[k * 16 + n4] : Wk4[k * 16 + (n4 - 16)];
    }
    // load xp tile: 2048 float4
    const float4* xp4 = (const float4*)(g_xp + (size_t)row0 * NH);
    float4* As4 = (float4*)As;
    #pragma unroll
    for (int i = 0; i < 8; i++) {
        int e = t + i * 256;
        As4[e] = xp4[e];
    }
    __syncthreads();

    int tx = t & 31;           // col group: n0 = tx*4 (consecutive)
    int ty = t >> 5;           // row group: m0 = ty*8 (uniform across warp -> broadcast a)
    int n0 = tx * 4, m0 = ty * 8;

    u64 acc[8][2] = {};
    #pragma unroll 4
    for (int k = 0; k < 128; k++) {
        ulonglong2 b2 = *(const ulonglong2*)&Bs[k * 128 + n0];  // 1x LDS.128, conflict-free
        #pragma unroll
        for (int i = 0; i < 8; i++) {
            u64 a2 = pack_dup(As[(m0 + i) * 128 + k]);          // warp-broadcast LDS.32
            fma2(acc[i][0], a2, b2.x);
            fma2(acc[i][1], a2, b2.y);
        }
    }

    #pragma unroll
    for (int i = 0; i < 8; i++) {
        int m = row0 + m0 + i;
        float2 p0 = unpack2(acc[i][0]);
        float2 p1 = unpack2(acc[i][1]);
        float4 v = make_float4(p0.x, p0.y, p1.x, p1.y);
        if (tx < 16) ((float4*)g_Q)[m * 16 + tx] = v;
        else         ((float4*)g_K)[m * 16 + (tx - 16)] = v;
    }
}

// ---------------- kernel 5: u = xp @ wvf (one warp per row) -----------------------
__global__ void k_u() {
    int w = (blockIdx.x * blockDim.x + threadIdx.x) >> 5;  // row 0..32767
    int lane = threadIdx.x & 31;
    const float* r = g_xp + (size_t)w * NH;
    float s = r[lane]      * g_wvf[lane]
            + r[lane + 32] * g_wvf[lane + 32]
            + r[lane + 64] * g_wvf[lane + 64]
            + r[lane + 96] * g_wvf[lane + 96];
    #pragma unroll
    for (int off = 16; off; off >>= 1) s += __shfl_down_sync(0xffffffffu, s, off);
    if (lane == 0) g_u[w] = s;
}

// ---------------- kernel 6: zero Z (fresh every launch; graph-replayed) -----------
__global__ void k_zero() {
    g_Z[blockIdx.x * blockDim.x + threadIdx.x] = 0.f;
}

// ---------------- kernel 7: E = exp(Q K^T / 8), Z += colsum(E) --------------------
// Per batch: 128x128 tile per CTA, depth 64 fully staged. 256 threads, 8x8 microtile.
// K-tile columns per thread at stride 16 (n = tx + 16j): 16 distinct banks with the
// 65-float row pad, upper half-warp broadcasts -> conflict-free inner loop, no transpose.
__global__ __launch_bounds__(256, 2) void k_scores() {
    extern __shared__ float sm[];
    float* Qs = sm;              // [128][65]
    float* Ks = sm + 128 * 65;   // [128][65]

    int t = threadIdx.x;
    int b = blockIdx.z;
    int q0 = blockIdx.y * 128;
    int k0 = blockIdx.x * 128;

    const float* Qg = g_Q + ((size_t)b * NS + q0) * ND;
    const float* Kg = g_K + ((size_t)b * NS + k0) * ND;

    #pragma unroll
    for (int i = 0; i < 32; i++) {
        int e = t + i * 256;           // 8192 elems per tile
        int r = e >> 6, d = e & 63;
        Qs[r * 65 + d] = Qg[e];
        Ks[r * 65 + d] = Kg[e];
    }
    __syncthreads();

    int tx = t & 15;           // cols: n = tx + 16j, j=0..7
    int ty = t >> 4;           // rows: m0 = ty*8
    int m0 = ty * 8;

    u64 acc[8][4] = {};        // [row][col-pair]; pair jp = cols (tx+32jp, tx+32jp+16)

    #pragma unroll 4
    for (int kk = 0; kk < 64; kk++) {
        u64 b2[4];
        #pragma unroll
        for (int jp = 0; jp < 4; jp++) {
            float blo = Ks[(tx + 32 * jp) * 65 + kk];
            float bhi = Ks[(tx + 32 * jp + 16) * 65 + kk];
            b2[jp] = pack2(blo, bhi);
        }
        #pragma unroll
        for (int i = 0; i < 8; i++) {
            u64 a2 = pack_dup(Qs[(m0 + i) * 65 + kk]);   // half-warp broadcast
            fma2(acc[i][0], a2, b2[0]);
            fma2(acc[i][1], a2, b2[1]);
            fma2(acc[i][2], a2, b2[2]);
            fma2(acc[i][3], a2, b2[3]);
        }
    }

    // epilogue: exp, store E, per-thread column partial sums
    float csum[8] = {0.f, 0.f, 0.f, 0.f, 0.f, 0.f, 0.f, 0.f};
    size_t ebase = ((size_t)b * NS + (q0 + m0)) * NS + k0;
    #pragma unroll
    for (int i = 0; i < 8; i++) {
        #pragma unroll
        for (int jp = 0; jp < 4; jp++) {
            float2 v = unpack2(acc[i][jp]);
            float e0 = __expf(v.x * 0.125f);
            float e1 = __expf(v.y * 0.125f);
            g_E[ebase + (size_t)i * NS + tx + 32 * jp]      = e0;
            g_E[ebase + (size_t)i * NS + tx + 32 * jp + 16] = e1;
            csum[2 * jp]     += e0;
            csum[2 * jp + 1] += e1;
        }
    }

    __syncthreads();             // done with Qs; reuse as reduction buffer
    float* red = sm;             // [16][128]
    #pragma unroll
    for (int j = 0; j < 8; j++) red[ty * 128 + tx + 16 * j] = csum[j];
    __syncthreads();

    if (t < 128) {
        float z = 0.f;
        #pragma unroll
        for (int r = 0; r < 16; r++) z += red[r * 128 + t];
        atomicAdd(&g_Z[b * NS + k0 + t], z);
    }
}

// ---------------- kernel 8: w = u / Z ---------------------------------------------
__global__ void k_w() {
    int i = blockIdx.x * blockDim.x + threadIdx.x;
    g_w[i] = g_u[i] / g_Z[i];
}

// ---------------- kernel 9: out[b,q] = E[b,q,:] . w[b,:] + bf ---------------------
__global__ __launch_bounds__(256) void k_out(const float* __restrict__ bf,
                                             float* __restrict__ out) {
    __shared__ float red[256];
    int rq = blockIdx.x;               // b*2048 + q
    int b = rq >> 11;
    int t = threadIdx.x;
    const float4* E4 = (const float4*)(g_E + (size_t)rq * NS);
    const float4* w4 = (const float4*)(g_w + b * NS);
    float s = 0.f;
    #pragma unroll
    for (int i = 0; i < 2; i++) {
        float4 e = E4[t + i * 256];
        float4 w = w4[t + i * 256];
        s += e.x * w.x + e.y * w.y + e.z * w.z + e.w * w.w;
    }
    red[t] = s;
    __syncthreads();
    #pragma unroll
    for (int off = 128; off > 0; off >>= 1) {
        if (t < off) red[t] += red[t + off];
        __syncthreads();
    }
    if (t == 0) out[rq] = red[0] + bf[0];
}

// ---------------- host launcher ---------------------------------------------------
extern "C" void kernel_launch(void* const* d_in, const int* in_sizes, int n_in,
                              void* d_out, int out_size) {
    (void)in_sizes; (void)n_in; (void)out_size;
    const float* x  = (const float*)d_in[0];
    const float* Wq = (const float*)d_in[1];
    const float* Wk = (const float*)d_in[2];
    const float* Wv = (const float*)d_in[3];
    const float* Wf = (const float*)d_in[4];
    const float* bf = (const float*)d_in[5];
    float* out = (float*)d_out;

    cudaFuncSetAttribute(k_proj,   cudaFuncAttributeMaxDynamicSharedMemorySize, 98304);
    cudaFuncSetAttribute(k_scores, cudaFuncAttributeMaxDynamicSharedMemorySize, 66560);

    k_pe<<<NS, 64>>>();
    k_xp<<<(NB * NS * NH) / 256, 256>>>(x);
    k_wvf<<<1, 128>>>(Wv, Wf);
    k_proj<<<(NB * NS) / 64, 256, 98304>>>(Wq, Wk);
    k_u<<<(NB * NS) / 8, 256>>>();
    k_zero<<<(NB * NS) / 256, 256>>>();
    dim3 sg(16, 16, 16);   // (k-tiles, q-tiles, batch)
    k_scores<<<sg, 256, 66560>>>();
    k_w<<<(NB * NS) / 256, 256>>>();
    k_out<<<NB * NS, 256>>>(bf, out);
}

// round 2
// speedup vs baseline: 1.0391x; 1.0391x over previous
#include <cuda_runtime.h>
#include <cuda_fp16.h>
#include <math.h>

#define NB 16
#define NS 2048
#define NH 128
#define ND 64

typedef unsigned long long u64;

// ---------------- scratch (device globals; no allocation allowed) ----------------
__device__ float g_pe[NS * NH];                 // 1 MB
__device__ float g_xp[NB * NS * NH];            // 16.8 MB
__device__ float g_Q[NB * NS * ND];             // 8.4 MB
__device__ float g_K[NB * NS * ND];             // 8.4 MB
__device__ float g_wvf[NH];
__device__ float g_u[NB * NS];
__device__ float g_Z[NB * NS];
__device__ float g_w[NB * NS];
__device__ __half g_Eh[(size_t)NB * NS * NS];   // 134 MB: exp(scores)/16 in fp16

// ---------------- packed fp32x2 helpers (FFMA2: 2x fp32 FMA rate on sm_103a) ------
__device__ __forceinline__ u64 pack_dup(float a) {
    u64 r; asm("mov.b64 %0, {%1,%1};" : "=l"(r) : "f"(a)); return r;
}
__device__ __forceinline__ void fma2(u64& c, u64 a, u64 b) {
    asm("fma.rn.f32x2 %0, %1, %2, %0;" : "+l"(c) : "l"(a), "l"(b));
}
__device__ __forceinline__ float2 unpack2(u64 v) {
    float lo, hi; asm("mov.b64 {%0,%1}, %2;" : "=f"(lo), "=f"(hi) : "l"(v));
    return make_float2(lo, hi);
}

// ---------------- kernel 1: sinusoidal PE (cheap: 1 fp64 exp2 + reduction) --------
__global__ void k_pe() {
    int p = blockIdx.x;     // 0..2047
    int i = threadIdx.x;    // 0..63
    // inv_rate = 10000^(-i/64) = 2^(-i * log2(10000)/64)
    double inv_rate = exp2(-(double)i * 0.20762050593046016);
    double ang = (double)p * inv_rate;                      // exact-ish in double
    double k = rint(ang * 0.15915494309189535);             // 1/(2*pi)
    double r = fma(-k, 6.283185307179586, ang);             // two-part 2*pi reduction
    r = fma(-k, 2.4492935982947064e-16, r);
    float s, c;
    sincosf((float)r, &s, &c);
    g_pe[p * NH + 2 * i]     = s;
    g_pe[p * NH + 2 * i + 1] = c;
}

// ---------------- kernel 2: xp = x + pe (broadcast over batch) --------------------
__global__ void k_xp(const float* __restrict__ x) {
    int idx = blockIdx.x * blockDim.x + threadIdx.x;   // grid covers NB*NS*NH exactly
    g_xp[idx] = x[idx] + g_pe[idx & (NS * NH - 1)];
}

// ---------------- kernel 3: wvf = Wv @ Wf  (fold V and output proj) ---------------
__global__ void k_wvf(const float* __restrict__ Wv, const float* __restrict__ Wf) {
    int h = threadIdx.x;  // 128
    float s = 0.f;
    #pragma unroll 8
    for (int d = 0; d < ND; d++) s += Wv[h * ND + d] * Wf[d];
    g_wvf[h] = s;
}

// ---------------- kernel 4: projections Q = xp@Wq, K = xp@Wk ----------------------
__global__ __launch_bounds__(256, 2) void k_proj(const float* __restrict__ Wq,
                                                 const float* __restrict__ Wk) {
    extern __shared__ float sm[];
    float* As = sm;              // [64][128] row-major
    float* Bs = sm + 64 * 128;   // [128][128] (k-major): col<64 -> Wq, else Wk

    int t = threadIdx.x;
    int row0 = blockIdx.x * 64;

    const float4* Wq4 = (const float4*)Wq;
    const float4* Wk4 = (const float4*)Wk;
    float4* Bs4 = (float4*)Bs;
    #pragma unroll
    for (int i = 0; i < 16; i++) {
        int e = t + i * 256;           // float4 index over [128][32]
        int k = e >> 5, n4 = e & 31;
        Bs4[e] = (n4 < 16) ? Wq4[k * 16 + n4] : Wk4[k * 16 + (n4 - 16)];
    }
    const float4* xp4 = (const float4*)(g_xp + (size_t)row0 * NH);
    float4* As4 = (float4*)As;
    #pragma unroll
    for (int i = 0; i < 8; i++) {
        int e = t + i * 256;
        As4[e] = xp4[e];
    }
    __syncthreads();

    int tx = t & 31;
    int ty = t >> 5;
    int n0 = tx * 4, m0 = ty * 8;

    u64 acc[8][2] = {};
    #pragma unroll 4
    for (int k = 0; k < 128; k++) {
        ulonglong2 b2 = *(const ulonglong2*)&Bs[k * 128 + n0];
        #pragma unroll
        for (int i = 0; i < 8; i++) {
            u64 a2 = pack_dup(As[(m0 + i) * 128 + k]);
            fma2(acc[i][0], a2, b2.x);
            fma2(acc[i][1], a2, b2.y);
        }
    }

    #pragma unroll
    for (int i = 0; i < 8; i++) {
        int m = row0 + m0 + i;
        float2 p0 = unpack2(acc[i][0]);
        float2 p1 = unpack2(acc[i][1]);
        float4 v = make_float4(p0.x, p0.y, p1.x, p1.y);
        if (tx < 16) ((float4*)g_Q)[m * 16 + tx] = v;
        else         ((float4*)g_K)[m * 16 + (tx - 16)] = v;
    }
}

// ---------------- kernel 5: u = xp @ wvf (one warp per row) -----------------------
__global__ void k_u() {
    int w = (blockIdx.x * blockDim.x + threadIdx.x) >> 5;  // row 0..32767
    int lane = threadIdx.x & 31;
    const float* r = g_xp + (size_t)w * NH;
    float s = r[lane]      * g_wvf[lane]
            + r[lane + 32] * g_wvf[lane + 32]
            + r[lane + 64] * g_wvf[lane + 64]
            + r[lane + 96] * g_wvf[lane + 96];
    #pragma unroll
    for (int off = 16; off; off >>= 1) s += __shfl_down_sync(0xffffffffu, s, off);
    if (lane == 0) g_u[w] = s;
}

// ---------------- kernel 6: zero Z (fresh every graph replay) ---------------------
__global__ void k_zero() {
    g_Z[blockIdx.x * blockDim.x + threadIdx.x] = 0.f;
}

// ---------------- kernel 7: E = exp(QK^T/8)/16 (fp16), Z += colsum ----------------
// 128x128 tile per CTA, depth 64 staged. 256 threads, 8 rows x 8 cols microtile.
// K staged TRANSPOSED [kk][n] (stride 132, 16B-aligned rows) -> B operand is two
// LDS.128 giving 4 ready f32x2 pairs. Q staged PRE-DUPLICATED as u64 pairs ->
// A operand is one broadcast LDS.64. Inner loop: 10 LDS + 32 FFMA2.
__global__ __launch_bounds__(256, 2) void k_scores() {
    extern __shared__ float sm[];
    float* Kst = sm;                          // [64][132] floats = 33792 B
    u64*   Qsd = (u64*)(sm + 64 * 132);       // [128][64] dup pairs = 65536 B

    int t = threadIdx.x;
    int b = blockIdx.z;
    int q0 = blockIdx.y * 128;
    int k0 = blockIdx.x * 128;

    const float4* Qg4 = (const float4*)(g_Q + ((size_t)b * NS + q0) * ND);
    const float4* Kg4 = (const float4*)(g_K + ((size_t)b * NS + k0) * ND);

    #pragma unroll
    for (int i = 0; i < 8; i++) {
        int e = t + i * 256;          // float4 index over [128][16]
        int r = e >> 4, c4 = e & 15;  // row, depth-quad
        float4 q = Qg4[e];
        u64* dst = &Qsd[r * 64 + 4 * c4];
        dst[0] = pack_dup(q.x); dst[1] = pack_dup(q.y);
        dst[2] = pack_dup(q.z); dst[3] = pack_dup(q.w);
        float4 kv = Kg4[e];
        Kst[(4 * c4 + 0) * 132 + r] = kv.x;
        Kst[(4 * c4 + 1) * 132 + r] = kv.y;
        Kst[(4 * c4 + 2) * 132 + r] = kv.z;
        Kst[(4 * c4 + 3) * 132 + r] = kv.w;
    }
    __syncthreads();

    int tx = t & 15;            // col group: cols 4tx..4tx+3 and 64+4tx..64+4tx+3
    int ty = t >> 4;            // row group: rows ty*8..ty*8+7
    int m0 = ty * 8, c0 = 4 * tx;

    u64 acc[8][4] = {};
    #pragma unroll 4
    for (int kk = 0; kk < 64; kk++) {
        ulonglong2 bA = *(const ulonglong2*)&Kst[kk * 132 + c0];
        ulonglong2 bB = *(const ulonglong2*)&Kst[kk * 132 + 64 + c0];
        const u64* qp = &Qsd[m0 * 64 + kk];
        #pragma unroll
        for (int i = 0; i < 8; i++) {
            u64 a = qp[i * 64];               // broadcast LDS.64 (pre-dup'd)
            fma2(acc[i][0], a, bA.x);
            fma2(acc[i][1], a, bA.y);
            fma2(acc[i][2], a, bB.x);
            fma2(acc[i][3], a, bB.y);
        }
    }

    // epilogue: exp (scaled by 1/16 -- scale-invariant through w=u/Z), fp16 store
    float csum[8] = {0.f, 0.f, 0.f, 0.f, 0.f, 0.f, 0.f, 0.f};
    size_t ebase = ((size_t)b * NS + (q0 + m0)) * NS + k0;
    #pragma unroll
    for (int i = 0; i < 8; i++) {
        float2 v0 = unpack2(acc[i][0]);
        float2 v1 = unpack2(acc[i][1]);
        float2 v2 = unpack2(acc[i][2]);
        float2 v3 = unpack2(acc[i][3]);
        float e0 = __expf(v0.x * 0.125f) * 0.0625f;
        float e1 = __expf(v0.y * 0.125f) * 0.0625f;
        float e2 = __expf(v1.x * 0.125f) * 0.0625f;
        float e3 = __expf(v1.y * 0.125f) * 0.0625f;
        float e4 = __expf(v2.x * 0.125f) * 0.0625f;
        float e5 = __expf(v2.y * 0.125f) * 0.0625f;
        float e6 = __expf(v3.x * 0.125f) * 0.0625f;
        float e7 = __expf(v3.y * 0.125f) * 0.0625f;
        __half2 h01 = __floats2half2_rn(e0, e1);
        __half2 h23 = __floats2half2_rn(e2, e3);
        __half2 h45 = __floats2half2_rn(e4, e5);
        __half2 h67 = __floats2half2_rn(e6, e7);
        uint2 pkA = make_uint2(*(unsigned*)&h01, *(unsigned*)&h23);
        uint2 pkB = make_uint2(*(unsigned*)&h45, *(unsigned*)&h67);
        *(uint2*)(g_Eh + ebase + (size_t)i * NS + c0)      = pkA;
        *(uint2*)(g_Eh + ebase + (size_t)i * NS + 64 + c0) = pkB;
        csum[0] += e0; csum[1] += e1; csum[2] += e2; csum[3] += e3;
        csum[4] += e4; csum[5] += e5; csum[6] += e6; csum[7] += e7;
    }

    __syncthreads();             // done with smem tiles; reuse for reduction
    float* red = sm;             // [16][128]
    #pragma unroll
    for (int j = 0; j < 4; j++) {
        red[ty * 128 + c0 + j]      = csum[j];
        red[ty * 128 + 64 + c0 + j] = csum[4 + j];
    }
    __syncthreads();

    if (t < 128) {
        float z = 0.f;
        #pragma unroll
        for (int r = 0; r < 16; r++) z += red[r * 128 + t];
        atomicAdd(&g_Z[b * NS + k0 + t], z);
    }
}

// ---------------- kernel 8: w = u / Z ---------------------------------------------
__global__ void k_w() {
    int i = blockIdx.x * blockDim.x + threadIdx.x;
    g_w[i] = g_u[i] / g_Z[i];
}

// ---------------- kernel 9: out[b,q] = E[b,q,:] . w[b,:] + bf ---------------------
__global__ __launch_bounds__(256) void k_out(const float* __restrict__ bf,
                                             float* __restrict__ out) {
    __shared__ float red[256];
    int rq = blockIdx.x;               // b*2048 + q
    int b = rq >> 11;
    int t = threadIdx.x;
    const uint2*  E2 = (const uint2*)(g_Eh + (size_t)rq * NS);   // 512 x 4 halves
    const float4* w4 = (const float4*)(g_w + b * NS);
    float s = 0.f;
    #pragma unroll
    for (int i = 0; i < 2; i++) {
        int j = t + i * 256;
        uint2 e = E2[j];
        __half2 h0 = *(__half2*)&e.x;
        __half2 h1 = *(__half2*)&e.y;
        float2 f0 = __half22float2(h0);
        float2 f1 = __half22float2(h1);
        float4 w = w4[j];
        s += f0.x * w.x + f0.y * w.y + f1.x * w.z + f1.y * w.w;
    }
    red[t] = s;
    __syncthreads();
    #pragma unroll
    for (int off = 128; off > 0; off >>= 1) {
        if (t < off) red[t] += red[t + off];
        __syncthreads();
    }
    if (t == 0) out[rq] = red[0] + bf[0];
}

// ---------------- host launcher ---------------------------------------------------
extern "C" void kernel_launch(void* const* d_in, const int* in_sizes, int n_in,
                              void* d_out, int out_size) {
    (void)in_sizes; (void)n_in; (void)out_size;
    const float* x  = (const float*)d_in[0];
    const float* Wq = (const float*)d_in[1];
    const float* Wk = (const float*)d_in[2];
    const float* Wv = (const float*)d_in[3];
    const float* Wf = (const float*)d_in[4];
    const float* bf = (const float*)d_in[5];
    float* out = (float*)d_out;

    cudaFuncSetAttribute(k_proj,   cudaFuncAttributeMaxDynamicSharedMemorySize, 98304);
    cudaFuncSetAttribute(k_scores, cudaFuncAttributeMaxDynamicSharedMemorySize, 99328);

    k_pe<<<NS, 64>>>();
    k_xp<<<(NB * NS * NH) / 256, 256>>>(x);
    k_wvf<<<1, 128>>>(Wv, Wf);
    k_proj<<<(NB * NS) / 64, 256, 98304>>>(Wq, Wk);
    k_u<<<(NB * NS) / 8, 256>>>();
    k_zero<<<(NB * NS) / 256, 256>>>();
    dim3 sg(16, 16, 16);   // (k-tiles, q-tiles, batch)
    k_scores<<<sg, 256, 99328>>>();
    k_w<<<(NB * NS) / 256, 256>>>();
    k_out<<<NB * NS, 256>>>(bf, out);
}

// round 4
// speedup vs baseline: 1.4286x; 1.3749x over previous
#include <cuda_runtime.h>
#include <cuda_fp16.h>
#include <cuda_bf16.h>
#include <math.h>
#include <stdint.h>

#define NB 16
#define NS 2048
#define NH 128
#define ND 64

typedef unsigned long long u64;

// ---------------- scratch (device globals; no allocation allowed) ----------------
__device__ float g_pe[NS * NH];
__device__ float g_xp[NB * NS * NH];
__device__ float g_Q[NB * NS * ND];
__device__ float g_K[NB * NS * ND];
__device__ float g_wvf[NH];
__device__ float g_u[NB * NS];
__device__ float g_Z[NB * NS];
__device__ float g_w[NB * NS];
__device__ __half g_Eh[(size_t)NB * NS * NS];   // 134 MB: exp(scores)/16 in fp16

// ---------------- packed fp32x2 helpers -------------------------------------------
__device__ __forceinline__ u64 pack_dup(float a) {
    u64 r; asm("mov.b64 %0, {%1,%1};" : "=l"(r) : "f"(a)); return r;
}
__device__ __forceinline__ void fma2(u64& c, u64 a, u64 b) {
    asm("fma.rn.f32x2 %0, %1, %2, %0;" : "+l"(c) : "l"(a), "l"(b));
}
__device__ __forceinline__ float2 unpack2(u64 v) {
    float lo, hi; asm("mov.b64 {%0,%1}, %2;" : "=f"(lo), "=f"(hi) : "l"(v));
    return make_float2(lo, hi);
}

// ---------------- legacy tensor-core helpers (base-target safe) -------------------
__device__ __forceinline__ uint32_t smem_u32(const void* p) {
    uint32_t a;
    asm("{ .reg .u64 t; cvta.to.shared.u64 t, %1; cvt.u32.u64 %0, t; }" : "=r"(a) : "l"(p));
    return a;
}
__device__ __forceinline__ void ldm_x4(uint32_t* r, uint32_t addr) {
    asm volatile("ldmatrix.sync.aligned.m8n8.x4.shared.b16 {%0,%1,%2,%3}, [%4];"
                 : "=r"(r[0]), "=r"(r[1]), "=r"(r[2]), "=r"(r[3]) : "r"(addr));
}
__device__ __forceinline__ void mma_bf16(float* c, const uint32_t* a,
                                         uint32_t b0, uint32_t b1) {
    asm volatile(
        "mma.sync.aligned.m16n8k16.row.col.f32.bf16.bf16.f32 "
        "{%0,%1,%2,%3}, {%4,%5,%6,%7}, {%8,%9}, {%0,%1,%2,%3};"
        : "+f"(c[0]), "+f"(c[1]), "+f"(c[2]), "+f"(c[3])
        : "r"(a[0]), "r"(a[1]), "r"(a[2]), "r"(a[3]), "r"(b0), "r"(b1));
}

// ---------------- kernel 1: sinusoidal PE -----------------------------------------
__global__ void k_pe() {
    int p = blockIdx.x;
    int i = threadIdx.x;  // 0..63
    double inv_rate = exp2(-(double)i * 0.20762050593046016);  // 10000^(-i/64)
    double ang = (double)p * inv_rate;
    double k = rint(ang * 0.15915494309189535);
    double r = fma(-k, 6.283185307179586, ang);
    r = fma(-k, 2.4492935982947064e-16, r);
    float s, c;
    sincosf((float)r, &s, &c);
    g_pe[p * NH + 2 * i]     = s;
    g_pe[p * NH + 2 * i + 1] = c;
}

// ---------------- kernel 2: xp = x + pe -------------------------------------------
__global__ void k_xp(const float* __restrict__ x) {
    int idx = blockIdx.x * blockDim.x + threadIdx.x;
    g_xp[idx] = x[idx] + g_pe[idx & (NS * NH - 1)];
}

// ---------------- kernel 3: wvf = Wv @ Wf -----------------------------------------
__global__ void k_wvf(const float* __restrict__ Wv, const float* __restrict__ Wf) {
    int h = threadIdx.x;
    float s = 0.f;
    #pragma unroll 8
    for (int d = 0; d < ND; d++) s += Wv[h * ND + d] * Wf[d];
    g_wvf[h] = s;
}

// ---------------- kernel 4: projections Q = xp@Wq, K = xp@Wk (FFMA2 SIMT) ---------
__global__ __launch_bounds__(256, 2) void k_proj(const float* __restrict__ Wq,
                                                 const float* __restrict__ Wk) {
    extern __shared__ float sm[];
    float* As = sm;
    float* Bs = sm + 64 * 128;

    int t = threadIdx.x;
    int row0 = blockIdx.x * 64;

    const float4* Wq4 = (const float4*)Wq;
    const float4* Wk4 = (const float4*)Wk;
    float4* Bs4 = (float4*)Bs;
    #pragma unroll
    for (int i = 0; i < 16; i++) {
        int e = t + i * 256;
        int k = e >> 5, n4 = e & 31;
        Bs4[e] = (n4 < 16) ? Wq4[k * 16 + n4] : Wk4[k * 16 + (n4 - 16)];
    }
    const float4* xp4 = (const float4*)(g_xp + (size_t)row0 * NH);
    float4* As4 = (float4*)As;
    #pragma unroll
    for (int i = 0; i < 8; i++) As4[t + i * 256] = xp4[t + i * 256];
    __syncthreads();

    int tx = t & 31, ty = t >> 5;
    int n0 = tx * 4, m0 = ty * 8;

    u64 acc[8][2] = {};
    #pragma unroll 4
    for (int k = 0; k < 128; k++) {
        ulonglong2 b2 = *(const ulonglong2*)&Bs[k * 128 + n0];
        #pragma unroll
        for (int i = 0; i < 8; i++) {
            u64 a2 = pack_dup(As[(m0 + i) * 128 + k]);
            fma2(acc[i][0], a2, b2.x);
            fma2(acc[i][1], a2, b2.y);
        }
    }
    #pragma unroll
    for (int i = 0; i < 8; i++) {
        int m = row0 + m0 + i;
        float2 p0 = unpack2(acc[i][0]);
        float2 p1 = unpack2(acc[i][1]);
        float4 v = make_float4(p0.x, p0.y, p1.x, p1.y);
        if (tx < 16) ((float4*)g_Q)[m * 16 + tx] = v;
        else         ((float4*)g_K)[m * 16 + (tx - 16)] = v;
    }
}

// ---------------- kernel 5: u = xp @ wvf ------------------------------------------
__global__ void k_u() {
    int w = (blockIdx.x * blockDim.x + threadIdx.x) >> 5;
    int lane = threadIdx.x & 31;
    const float* r = g_xp + (size_t)w * NH;
    float s = r[lane]      * g_wvf[lane]
            + r[lane + 32] * g_wvf[lane + 32]
            + r[lane + 64] * g_wvf[lane + 64]
            + r[lane + 96] * g_wvf[lane + 96];
    #pragma unroll
    for (int off = 16; off; off >>= 1) s += __shfl_down_sync(0xffffffffu, s, off);
    if (lane == 0) g_u[w] = s;
}

// ---------------- kernel 6: zero Z ------------------------------------------------
__global__ void k_zero() {
    g_Z[blockIdx.x * blockDim.x + threadIdx.x] = 0.f;
}

// ---------------- kernel 7: E = exp(QK^T/8)/16 via mma.sync bf16 3-pass -----------
// 128x128 tile per CTA, 8 warps (4m x 2n), warp tile 32x64.
// Q,K split into bf16 hi+lo; scores = QhKh + QhKl + QlKh (fp32 accum).
// smem tiles [128 rows][72 halves] pitch -> conflict-free ldmatrix (bank stride 4r).
// In-kernel Z colsum: shfl_xor over g-groups, then global atomics.
__global__ __launch_bounds__(256, 2) void k_scores() {
    extern __shared__ __align__(16) __nv_bfloat16 smh[];
    const int PITCH = 72;
    __nv_bfloat16* QH = smh;                     // [128][72]
    __nv_bfloat16* QL = smh + 128 * PITCH;
    __nv_bfloat16* KH = smh + 2 * 128 * PITCH;
    __nv_bfloat16* KL = smh + 3 * 128 * PITCH;

    int t = threadIdx.x;
    int w = t >> 5, lane = t & 31;
    int b = blockIdx.z;
    int q0 = blockIdx.y * 128;
    int k0 = blockIdx.x * 128;

    // stage: fp32 -> bf16 hi/lo
    const float4* Qg4 = (const float4*)(g_Q + ((size_t)b * NS + q0) * ND);
    const float4* Kg4 = (const float4*)(g_K + ((size_t)b * NS + k0) * ND);
    #pragma unroll
    for (int i = 0; i < 8; i++) {
        int e = t + i * 256;          // float4 index over [128 rows][16 quads]
        int r = e >> 4, c4 = e & 15;
        int off = r * PITCH + c4 * 4; // halves

        float4 q = Qg4[e];
        __nv_bfloat16 h0 = __float2bfloat16_rn(q.x), h1 = __float2bfloat16_rn(q.y);
        __nv_bfloat16 h2 = __float2bfloat16_rn(q.z), h3 = __float2bfloat16_rn(q.w);
        uint2 hi = make_uint2(
            (uint32_t)__bfloat16_as_ushort(h0) | ((uint32_t)__bfloat16_as_ushort(h1) << 16),
            (uint32_t)__bfloat16_as_ushort(h2) | ((uint32_t)__bfloat16_as_ushort(h3) << 16));
        __nv_bfloat162 l01 = __floats2bfloat162_rn(q.x - __bfloat162float(h0),
                                                   q.y - __bfloat162float(h1));
        __nv_bfloat162 l23 = __floats2bfloat162_rn(q.z - __bfloat162float(h2),
                                                   q.w - __bfloat162float(h3));
        *(uint2*)(QH + off) = hi;
        *(uint2*)(QL + off) = make_uint2(*(uint32_t*)&l01, *(uint32_t*)&l23);

        float4 kv = Kg4[e];
        h0 = __float2bfloat16_rn(kv.x); h1 = __float2bfloat16_rn(kv.y);
        h2 = __float2bfloat16_rn(kv.z); h3 = __float2bfloat16_rn(kv.w);
        hi = make_uint2(
            (uint32_t)__bfloat16_as_ushort(h0) | ((uint32_t)__bfloat16_as_ushort(h1) << 16),
            (uint32_t)__bfloat16_as_ushort(h2) | ((uint32_t)__bfloat16_as_ushort(h3) << 16));
        l01 = __floats2bfloat162_rn(kv.x - __bfloat162float(h0), kv.y - __bfloat162float(h1));
        l23 = __floats2bfloat162_rn(kv.z - __bfloat162float(h2), kv.w - __bfloat162float(h3));
        *(uint2*)(KH + off) = hi;
        *(uint2*)(KL + off) = make_uint2(*(uint32_t*)&l01, *(uint32_t*)&l23);
    }
    __syncthreads();

    int warp_m = w & 3, warp_n = w >> 2;
    int m0 = warp_m * 32, n0 = warp_n * 64;
    int lr = lane & 15;                 // ldmatrix row within 16
    int lc = (lane >> 4) << 3;          // ldmatrix col half-block (0 or 8)

    uint32_t aQH = smem_u32(QH), aQL = smem_u32(QL);
    uint32_t aKH = smem_u32(KH), aKL = smem_u32(KL);

    float acc[2][8][4] = {};

    #pragma unroll
    for (int pass = 0; pass < 3; pass++) {
        uint32_t Ab = (pass == 2) ? aQL : aQH;
        uint32_t Bb = (pass == 1) ? aKL : aKH;
        #pragma unroll
        for (int ks = 0; ks < 4; ks++) {
            int col = ks * 16 + lc;
            uint32_t a0[4], a1[4];
            ldm_x4(a0, Ab + ((m0 + lr) * PITCH + col) * 2);
            ldm_x4(a1, Ab + ((m0 + 16 + lr) * PITCH + col) * 2);
            #pragma unroll
            for (int nb = 0; nb < 4; nb++) {
                uint32_t bf[4];
                ldm_x4(bf, Bb + ((n0 + nb * 16 + lr) * PITCH + col) * 2);
                mma_bf16(acc[0][2 * nb],     a0, bf[0], bf[2]);
                mma_bf16(acc[0][2 * nb + 1], a0, bf[1], bf[3]);
                mma_bf16(acc[1][2 * nb],     a1, bf[0], bf[2]);
                mma_bf16(acc[1][2 * nb + 1], a1, bf[1], bf[3]);
            }
        }
    }

    // epilogue: exp/16 -> fp16 store + column partial sums
    int g = lane >> 2, tq = lane & 3;
    float csum[16];
    #pragma unroll
    for (int j = 0; j < 16; j++) csum[j] = 0.f;

    #pragma unroll
    for (int mi = 0; mi < 2; mi++) {
        int rlo = q0 + m0 + mi * 16 + g;
        __half* p0 = g_Eh + ((size_t)b * NS + rlo) * NS + k0 + n0;
        __half* p1 = p0 + (size_t)8 * NS;
        #pragma unroll
        for (int j = 0; j < 8; j++) {
            int c = j * 8 + 2 * tq;
            float e0 = __expf(acc[mi][j][0] * 0.125f) * 0.0625f;
            float e1 = __expf(acc[mi][j][1] * 0.125f) * 0.0625f;
            float e2 = __expf(acc[mi][j][2] * 0.125f) * 0.0625f;
            float e3 = __expf(acc[mi][j][3] * 0.125f) * 0.0625f;
            *(__half2*)(p0 + c) = __floats2half2_rn(e0, e1);
            *(__half2*)(p1 + c) = __floats2half2_rn(e2, e3);
            csum[2 * j]     += e0 + e2;
            csum[2 * j + 1] += e1 + e3;
        }
    }

    // reduce over g (8 groups) via shfl_xor; then lanes g==0 issue atomics
    #pragma unroll
    for (int off = 4; off <= 16; off <<= 1) {
        #pragma unroll
        for (int j = 0; j < 16; j++)
            csum[j] += __shfl_xor_sync(0xffffffffu, csum[j], off);
    }
    if (lane < 4) {
        float* zp = g_Z + b * NS + k0 + n0 + 2 * tq;
        #pragma unroll
        for (int j = 0; j < 8; j++) {
            atomicAdd(zp + j * 8,     csum[2 * j]);
            atomicAdd(zp + j * 8 + 1, csum[2 * j + 1]);
        }
    }
}

// ---------------- kernel 8: w = u / Z ---------------------------------------------
__global__ void k_w() {
    int i = blockIdx.x * blockDim.x + threadIdx.x;
    g_w[i] = g_u[i] / g_Z[i];
}

// ---------------- kernel 9: out[b,q] = E[b,q,:] . w[b,:] + bf ---------------------
__global__ __launch_bounds__(256) void k_out(const float* __restrict__ bf,
                                             float* __restrict__ out) {
    __shared__ float red[256];
    int rq = blockIdx.x;
    int b = rq >> 11;
    int t = threadIdx.x;
    const uint2*  E2 = (const uint2*)(g_Eh + (size_t)rq * NS);
    const float4* w4 = (const float4*)(g_w + b * NS);
    float s = 0.f;
    #pragma unroll
    for (int i = 0; i < 2; i++) {
        int j = t + i * 256;
        uint2 e = E2[j];
        float2 f0 = __half22float2(*(__half2*)&e.x);
        float2 f1 = __half22float2(*(__half2*)&e.y);
        float4 w = w4[j];
        s += f0.x * w.x + f0.y * w.y + f1.x * w.z + f1.y * w.w;
    }
    red[t] = s;
    __syncthreads();
    #pragma unroll
    for (int off = 128; off > 0; off >>= 1) {
        if (t < off) red[t] += red[t + off];
        __syncthreads();
    }
    if (t == 0) out[rq] = red[0] + bf[0];
}

// ---------------- host launcher ---------------------------------------------------
extern "C" void kernel_launch(void* const* d_in, const int* in_sizes, int n_in,
                              void* d_out, int out_size) {
    (void)in_sizes; (void)n_in; (void)out_size;
    const float* x  = (const float*)d_in[0];
    const float* Wq = (const float*)d_in[1];
    const float* Wk = (const float*)d_in[2];
    const float* Wv = (const float*)d_in[3];
    const float* Wf = (const float*)d_in[4];
    const float* bf = (const float*)d_in[5];
    float* out = (float*)d_out;

    cudaFuncSetAttribute(k_proj,   cudaFuncAttributeMaxDynamicSharedMemorySize, 98304);
    cudaFuncSetAttribute(k_scores, cudaFuncAttributeMaxDynamicSharedMemorySize, 73728);

    k_pe<<<NS, 64>>>();
    k_xp<<<(NB * NS * NH) / 256, 256>>>(x);
    k_wvf<<<1, 128>>>(Wv, Wf);
    k_proj<<<(NB * NS) / 64, 256, 98304>>>(Wq, Wk);
    k_u<<<(NB * NS) / 8, 256>>>();
    k_zero<<<(NB * NS) / 256, 256>>>();
    dim3 sg(16, 16, 16);   // (k-tiles, q-tiles, batch)
    k_scores<<<sg, 256, 73728>>>();
    k_w<<<(NB * NS) / 256, 256>>>();
    k_out<<<NB * NS, 256>>>(bf, out);
}

// round 5
// speedup vs baseline: 1.5553x; 1.0887x over previous
#include <cuda_runtime.h>
#include <cuda_fp16.h>
#include <cuda_bf16.h>
#include <math.h>
#include <stdint.h>

#define NB 16
#define NS 2048
#define NH 128
#define ND 64

typedef unsigned long long u64;

// ---------------- scratch (device globals; no allocation allowed) ----------------
__device__ float g_pe[NS * NH];
__device__ float g_xp[NB * NS * NH];
__device__ float g_Q[NB * NS * ND];
__device__ float g_K[NB * NS * ND];
__device__ float g_wvf[NH];
__device__ float g_u[NB * NS];
__device__ float g_Z[NB * NS];
__device__ float g_w[NB * NS];
__device__ __half g_Eh[(size_t)NB * NS * NS];   // 134 MB: exp(scores)/16 in fp16

// ---------------- packed fp32x2 helpers -------------------------------------------
__device__ __forceinline__ u64 pack_dup(float a) {
    u64 r; asm("mov.b64 %0, {%1,%1};" : "=l"(r) : "f"(a)); return r;
}
__device__ __forceinline__ void fma2(u64& c, u64 a, u64 b) {
    asm("fma.rn.f32x2 %0, %1, %2, %0;" : "+l"(c) : "l"(a), "l"(b));
}
__device__ __forceinline__ float2 unpack2(u64 v) {
    float lo, hi; asm("mov.b64 {%0,%1}, %2;" : "=f"(lo), "=f"(hi) : "l"(v));
    return make_float2(lo, hi);
}

// ---------------- legacy tensor-core helpers (base-target safe) -------------------
__device__ __forceinline__ uint32_t smem_u32(const void* p) {
    uint32_t a;
    asm("{ .reg .u64 t; cvta.to.shared.u64 t, %1; cvt.u32.u64 %0, t; }" : "=r"(a) : "l"(p));
    return a;
}
__device__ __forceinline__ void ldm_x4(uint32_t* r, uint32_t addr) {
    asm volatile("ldmatrix.sync.aligned.m8n8.x4.shared.b16 {%0,%1,%2,%3}, [%4];"
                 : "=r"(r[0]), "=r"(r[1]), "=r"(r[2]), "=r"(r[3]) : "r"(addr));
}
__device__ __forceinline__ void mma_bf16(float* c, const uint32_t* a,
                                         uint32_t b0, uint32_t b1) {
    asm volatile(
        "mma.sync.aligned.m16n8k16.row.col.f32.bf16.bf16.f32 "
        "{%0,%1,%2,%3}, {%4,%5,%6,%7}, {%8,%9}, {%0,%1,%2,%3};"
        : "+f"(c[0]), "+f"(c[1]), "+f"(c[2]), "+f"(c[3])
        : "r"(a[0]), "r"(a[1]), "r"(a[2]), "r"(a[3]), "r"(b0), "r"(b1));
}

// ---------------- kernel 1: sinusoidal PE -----------------------------------------
__global__ void k_pe() {
    int p = blockIdx.x;
    int i = threadIdx.x;  // 0..63
    double inv_rate = exp2(-(double)i * 0.20762050593046016);  // 10000^(-i/64)
    double ang = (double)p * inv_rate;
    double k = rint(ang * 0.15915494309189535);
    double r = fma(-k, 6.283185307179586, ang);
    r = fma(-k, 2.4492935982947064e-16, r);
    float s, c;
    sincosf((float)r, &s, &c);
    g_pe[p * NH + 2 * i]     = s;
    g_pe[p * NH + 2 * i + 1] = c;
}

// ---------------- kernel 2: xp = x + pe -------------------------------------------
__global__ void k_xp(const float* __restrict__ x) {
    int idx = blockIdx.x * blockDim.x + threadIdx.x;
    g_xp[idx] = x[idx] + g_pe[idx & (NS * NH - 1)];
}

// ---------------- kernel 3: wvf = Wv @ Wf -----------------------------------------
__global__ void k_wvf(const float* __restrict__ Wv, const float* __restrict__ Wf) {
    int h = threadIdx.x;
    float s = 0.f;
    #pragma unroll 8
    for (int d = 0; d < ND; d++) s += Wv[h * ND + d] * Wf[d];
    g_wvf[h] = s;
}

// ---------------- kernel 4: projections Q = xp@Wq, K = xp@Wk (FFMA2 SIMT) ---------
__global__ __launch_bounds__(256, 2) void k_proj(const float* __restrict__ Wq,
                                                 const float* __restrict__ Wk) {
    extern __shared__ float sm[];
    float* As = sm;
    float* Bs = sm + 64 * 128;

    int t = threadIdx.x;
    int row0 = blockIdx.x * 64;

    const float4* Wq4 = (const float4*)Wq;
    const float4* Wk4 = (const float4*)Wk;
    float4* Bs4 = (float4*)Bs;
    #pragma unroll
    for (int i = 0; i < 16; i++) {
        int e = t + i * 256;
        int k = e >> 5, n4 = e & 31;
        Bs4[e] = (n4 < 16) ? Wq4[k * 16 + n4] : Wk4[k * 16 + (n4 - 16)];
    }
    const float4* xp4 = (const float4*)(g_xp + (size_t)row0 * NH);
    float4* As4 = (float4*)As;
    #pragma unroll
    for (int i = 0; i < 8; i++) As4[t + i * 256] = xp4[t + i * 256];
    __syncthreads();

    int tx = t & 31, ty = t >> 5;
    int n0 = tx * 4, m0 = ty * 8;

    u64 acc[8][2] = {};
    #pragma unroll 4
    for (int k = 0; k < 128; k++) {
        ulonglong2 b2 = *(const ulonglong2*)&Bs[k * 128 + n0];
        #pragma unroll
        for (int i = 0; i < 8; i++) {
            u64 a2 = pack_dup(As[(m0 + i) * 128 + k]);
            fma2(acc[i][0], a2, b2.x);
            fma2(acc[i][1], a2, b2.y);
        }
    }
    #pragma unroll
    for (int i = 0; i < 8; i++) {
        int m = row0 + m0 + i;
        float2 p0 = unpack2(acc[i][0]);
        float2 p1 = unpack2(acc[i][1]);
        float4 v = make_float4(p0.x, p0.y, p1.x, p1.y);
        if (tx < 16) ((float4*)g_Q)[m * 16 + tx] = v;
        else         ((float4*)g_K)[m * 16 + (tx - 16)] = v;
    }
}

// ---------------- kernel 5: u = xp @ wvf ------------------------------------------
__global__ void k_u() {
    int w = (blockIdx.x * blockDim.x + threadIdx.x) >> 5;
    int lane = threadIdx.x & 31;
    const float* r = g_xp + (size_t)w * NH;
    float s = r[lane]      * g_wvf[lane]
            + r[lane + 32] * g_wvf[lane + 32]
            + r[lane + 64] * g_wvf[lane + 64]
            + r[lane + 96] * g_wvf[lane + 96];
    #pragma unroll
    for (int off = 16; off; off >>= 1) s += __shfl_down_sync(0xffffffffu, s, off);
    if (lane == 0) g_u[w] = s;
}

// ---------------- kernel 6: zero Z ------------------------------------------------
__global__ void k_zero() {
    g_Z[blockIdx.x * blockDim.x + threadIdx.x] = 0.f;
}

// ---------------- kernel 7: E = exp(QK^T/8)/16 via mma.sync bf16 3-pass -----------
// 128x128 tile per CTA, 8 warps (4m x 2n), warp tile 32x64.
// Q,K split into bf16 hi+lo; scores = QhKh + QhKl + QlKh (fp32 accum).
// Kh fragments register-cached across passes: 12 LDSM/kstep (was 18).
// Epilogue: exp -> smem (XOR-swizzled, conflict-free) -> coalesced STG.128.
__global__ __launch_bounds__(256, 2) void k_scores() {
    extern __shared__ __align__(16) __nv_bfloat16 smh[];
    const int PITCH = 72;
    __nv_bfloat16* QH = smh;                     // [128][72]
    __nv_bfloat16* QL = smh + 128 * PITCH;
    __nv_bfloat16* KH = smh + 2 * 128 * PITCH;
    __nv_bfloat16* KL = smh + 3 * 128 * PITCH;
    uint32_t* Esm = (uint32_t*)smh;              // epilogue reuse: [128][64] words (32KB)

    int t = threadIdx.x;
    int w = t >> 5, lane = t & 31;
    int b = blockIdx.z;
    int q0 = blockIdx.y * 128;
    int k0 = blockIdx.x * 128;

    // stage: fp32 -> bf16 hi/lo
    const float4* Qg4 = (const float4*)(g_Q + ((size_t)b * NS + q0) * ND);
    const float4* Kg4 = (const float4*)(g_K + ((size_t)b * NS + k0) * ND);
    #pragma unroll
    for (int i = 0; i < 8; i++) {
        int e = t + i * 256;          // float4 index over [128 rows][16 quads]
        int r = e >> 4, c4 = e & 15;
        int off = r * PITCH + c4 * 4; // halves

        float4 q = Qg4[e];
        __nv_bfloat16 h0 = __float2bfloat16_rn(q.x), h1 = __float2bfloat16_rn(q.y);
        __nv_bfloat16 h2 = __float2bfloat16_rn(q.z), h3 = __float2bfloat16_rn(q.w);
        uint2 hi = make_uint2(
            (uint32_t)__bfloat16_as_ushort(h0) | ((uint32_t)__bfloat16_as_ushort(h1) << 16),
            (uint32_t)__bfloat16_as_ushort(h2) | ((uint32_t)__bfloat16_as_ushort(h3) << 16));
        __nv_bfloat162 l01 = __floats2bfloat162_rn(q.x - __bfloat162float(h0),
                                                   q.y - __bfloat162float(h1));
        __nv_bfloat162 l23 = __floats2bfloat162_rn(q.z - __bfloat162float(h2),
                                                   q.w - __bfloat162float(h3));
        *(uint2*)(QH + off) = hi;
        *(uint2*)(QL + off) = make_uint2(*(uint32_t*)&l01, *(uint32_t*)&l23);

        float4 kv = Kg4[e];
        h0 = __float2bfloat16_rn(kv.x); h1 = __float2bfloat16_rn(kv.y);
        h2 = __float2bfloat16_rn(kv.z); h3 = __float2bfloat16_rn(kv.w);
        hi = make_uint2(
            (uint32_t)__bfloat16_as_ushort(h0) | ((uint32_t)__bfloat16_as_ushort(h1) << 16),
            (uint32_t)__bfloat16_as_ushort(h2) | ((uint32_t)__bfloat16_as_ushort(h3) << 16));
        l01 = __floats2bfloat162_rn(kv.x - __bfloat162float(h0), kv.y - __bfloat162float(h1));
        l23 = __floats2bfloat162_rn(kv.z - __bfloat162float(h2), kv.w - __bfloat162float(h3));
        *(uint2*)(KH + off) = hi;
        *(uint2*)(KL + off) = make_uint2(*(uint32_t*)&l01, *(uint32_t*)&l23);
    }
    __syncthreads();

    int warp_m = w & 3, warp_n = w >> 2;
    int m0 = warp_m * 32, n0 = warp_n * 64;
    int lr = lane & 15;                 // ldmatrix row within 16
    int lc = (lane >> 4) << 3;          // ldmatrix col half-block (0 or 8)

    uint32_t aQH = smem_u32(QH), aQL = smem_u32(QL);
    uint32_t aKH = smem_u32(KH), aKL = smem_u32(KL);

    float acc[2][8][4] = {};

    #pragma unroll
    for (int ks = 0; ks < 4; ks++) {
        int col = ks * 16 + lc;
        uint32_t a0[4], a1[4];
        // pass 0: Qh x Kh (cache Kh fragments in regs)
        ldm_x4(a0, aQH + ((m0 + lr) * PITCH + col) * 2);
        ldm_x4(a1, aQH + ((m0 + 16 + lr) * PITCH + col) * 2);
        uint32_t bkh[4][4];
        #pragma unroll
        for (int nb = 0; nb < 4; nb++)
            ldm_x4(bkh[nb], aKH + ((n0 + nb * 16 + lr) * PITCH + col) * 2);
        #pragma unroll
        for (int nb = 0; nb < 4; nb++) {
            mma_bf16(acc[0][2 * nb],     a0, bkh[nb][0], bkh[nb][2]);
            mma_bf16(acc[0][2 * nb + 1], a0, bkh[nb][1], bkh[nb][3]);
            mma_bf16(acc[1][2 * nb],     a1, bkh[nb][0], bkh[nb][2]);
            mma_bf16(acc[1][2 * nb + 1], a1, bkh[nb][1], bkh[nb][3]);
        }
        // pass 1: Qh x Kl (stream Kl)
        #pragma unroll
        for (int nb = 0; nb < 4; nb++) {
            uint32_t bkl[4];
            ldm_x4(bkl, aKL + ((n0 + nb * 16 + lr) * PITCH + col) * 2);
            mma_bf16(acc[0][2 * nb],     a0, bkl[0], bkl[2]);
            mma_bf16(acc[0][2 * nb + 1], a0, bkl[1], bkl[3]);
            mma_bf16(acc[1][2 * nb],     a1, bkl[0], bkl[2]);
            mma_bf16(acc[1][2 * nb + 1], a1, bkl[1], bkl[3]);
        }
        // pass 2: Ql x Kh (reuse cached Kh)
        ldm_x4(a0, aQL + ((m0 + lr) * PITCH + col) * 2);
        ldm_x4(a1, aQL + ((m0 + 16 + lr) * PITCH + col) * 2);
        #pragma unroll
        for (int nb = 0; nb < 4; nb++) {
            mma_bf16(acc[0][2 * nb],     a0, bkh[nb][0], bkh[nb][2]);
            mma_bf16(acc[0][2 * nb + 1], a0, bkh[nb][1], bkh[nb][3]);
            mma_bf16(acc[1][2 * nb],     a1, bkh[nb][0], bkh[nb][2]);
            mma_bf16(acc[1][2 * nb + 1], a1, bkh[nb][1], bkh[nb][3]);
        }
    }

    __syncthreads();   // staging tiles dead; smem becomes E transpose buffer

    // epilogue part 1: exp/16 -> smem (XOR swizzle), accumulate column sums
    int g = lane >> 2, tq = lane & 3;
    float csum[16];
    #pragma unroll
    for (int j = 0; j < 16; j++) csum[j] = 0.f;

    #pragma unroll
    for (int mi = 0; mi < 2; mi++) {
        int rl = m0 + mi * 16 + g;             // local row (rl & 7 == g)
        uint32_t* erow = Esm + rl * 64;
        int sw = (g & 7) * 4;
        #pragma unroll
        for (int j = 0; j < 8; j++) {
            float e0 = __expf(acc[mi][j][0] * 0.125f) * 0.0625f;
            float e1 = __expf(acc[mi][j][1] * 0.125f) * 0.0625f;
            float e2 = __expf(acc[mi][j][2] * 0.125f) * 0.0625f;
            float e3 = __expf(acc[mi][j][3] * 0.125f) * 0.0625f;
            __half2 hA = __floats2half2_rn(e0, e1);
            __half2 hB = __floats2half2_rn(e2, e3);
            int c2a = (n0 >> 1) + 4 * j + tq;            // rows rl and rl+8
            erow[c2a ^ sw] = *(uint32_t*)&hA;
            (erow + 8 * 64)[c2a ^ ((g & 7) * 4)] = *(uint32_t*)&hB;  // same g -> same sw
            csum[2 * j]     += e0 + e2;
            csum[2 * j + 1] += e1 + e3;
        }
    }

    // column-sum reduce over g groups, then atomics (before syncthreads: reg/shfl only)
    #pragma unroll
    for (int off = 4; off <= 16; off <<= 1) {
        #pragma unroll
        for (int j = 0; j < 16; j++)
            csum[j] += __shfl_xor_sync(0xffffffffu, csum[j], off);
    }
    if (lane < 4) {
        float* zp = g_Z + b * NS + k0 + n0 + 2 * tq;
        #pragma unroll
        for (int j = 0; j < 8; j++) {
            atomicAdd(zp + j * 8,     csum[2 * j]);
            atomicAdd(zp + j * 8 + 1, csum[2 * j + 1]);
        }
    }
    __syncthreads();

    // epilogue part 2: coalesced stream-out. Half-warp per row: 16 lanes x 16B = 256B.
    {
        int hw = (t >> 4);          // 0..15: half-warp id
        int h = t & 15;             // 16B chunk within row
        #pragma unroll
        for (int it = 0; it < 8; it++) {
            int r = it * 16 + hw;   // local row 0..127
            uint32_t wbase = r * 64;
            int sw = (r & 7) * 4;
            uint32_t w0 = (4 * h) ^ sw;
            uint4 v = *(uint4*)&Esm[wbase + w0];
            __half* dst = g_Eh + ((size_t)b * NS + q0 + r) * NS + k0 + 8 * h;
            *(uint4*)dst = v;
        }
    }
}

// ---------------- kernel 8: w = u / Z ---------------------------------------------
__global__ void k_w() {
    int i = blockIdx.x * blockDim.x + threadIdx.x;
    g_w[i] = g_u[i] / g_Z[i];
}

// ---------------- kernel 9: out[b,q] = E[b,q,:] . w[b,:] + bf ---------------------
__global__ __launch_bounds__(256) void k_out(const float* __restrict__ bf,
                                             float* __restrict__ out) {
    __shared__ float red[256];
    int rq = blockIdx.x;
    int b = rq >> 11;
    int t = threadIdx.x;
    const uint2*  E2 = (const uint2*)(g_Eh + (size_t)rq * NS);
    const float4* w4 = (const float4*)(g_w + b * NS);
    float s = 0.f;
    #pragma unroll
    for (int i = 0; i < 2; i++) {
        int j = t + i * 256;
        uint2 e = E2[j];
        float2 f0 = __half22float2(*(__half2*)&e.x);
        float2 f1 = __half22float2(*(__half2*)&e.y);
        float4 w = w4[j];
        s += f0.x * w.x + f0.y * w.y + f1.x * w.z + f1.y * w.w;
    }
    red[t] = s;
    __syncthreads();
    #pragma unroll
    for (int off = 128; off > 0; off >>= 1) {
        if (t < off) red[t] += red[t + off];
        __syncthreads();
    }
    if (t == 0) out[rq] = red[0] + bf[0];
}

// ---------------- host launcher ---------------------------------------------------
extern "C" void kernel_launch(void* const* d_in, const int* in_sizes, int n_in,
                              void* d_out, int out_size) {
    (void)in_sizes; (void)n_in; (void)out_size;
    const float* x  = (const float*)d_in[0];
    const float* Wq = (const float*)d_in[1];
    const float* Wk = (const float*)d_in[2];
    const float* Wv = (const float*)d_in[3];
    const float* Wf = (const float*)d_in[4];
    const float* bf = (const float*)d_in[5];
    float* out = (float*)d_out;

    cudaFuncSetAttribute(k_proj,   cudaFuncAttributeMaxDynamicSharedMemorySize, 98304);
    cudaFuncSetAttribute(k_scores, cudaFuncAttributeMaxDynamicSharedMemorySize, 73728);

    k_pe<<<NS, 64>>>();
    k_xp<<<(NB * NS * NH) / 256, 256>>>(x);
    k_wvf<<<1, 128>>>(Wv, Wf);
    k_proj<<<(NB * NS) / 64, 256, 98304>>>(Wq, Wk);
    k_u<<<(NB * NS) / 8, 256>>>();
    k_zero<<<(NB * NS) / 256, 256>>>();
    dim3 sg(16, 16, 16);   // (k-tiles, q-tiles, batch)
    k_scores<<<sg, 256, 73728>>>();
    k_w<<<(NB * NS) / 256, 256>>>();
    k_out<<<NB * NS, 256>>>(bf, out);
}

// round 6
// speedup vs baseline: 1.9395x; 1.2471x over previous
#include <cuda_runtime.h>
#include <cuda_fp16.h>
#include <math.h>
#include <stdint.h>

#define NB 16
#define NS 2048
#define NH 128
#define ND 64

typedef unsigned long long u64;

// ---------------- scratch (device globals; no allocation allowed) ----------------
__device__ float g_pe[NS * NH];
__device__ float g_xp[NB * NS * NH];
__device__ __half g_Qh[NB * NS * ND];           // fp16 Q (rounded once in k_proj)
__device__ __half g_Kh[NB * NS * ND];           // fp16 K
__device__ float g_wvf[NH];
__device__ float g_u[NB * NS];
__device__ float g_Z[NB * NS];
__device__ float g_w[NB * NS];
__device__ __half g_Eh[(size_t)NB * NS * NS];   // 134 MB: exp(scores)/16 in fp16

// ---------------- packed fp32x2 helpers -------------------------------------------
__device__ __forceinline__ u64 pack_dup(float a) {
    u64 r; asm("mov.b64 %0, {%1,%1};" : "=l"(r) : "f"(a)); return r;
}
__device__ __forceinline__ void fma2(u64& c, u64 a, u64 b) {
    asm("fma.rn.f32x2 %0, %1, %2, %0;" : "+l"(c) : "l"(a), "l"(b));
}
__device__ __forceinline__ float2 unpack2(u64 v) {
    float lo, hi; asm("mov.b64 {%0,%1}, %2;" : "=f"(lo), "=f"(hi) : "l"(v));
    return make_float2(lo, hi);
}

// ---------------- legacy tensor-core helpers (base-target safe) -------------------
__device__ __forceinline__ uint32_t smem_u32(const void* p) {
    uint32_t a;
    asm("{ .reg .u64 t; cvta.to.shared.u64 t, %1; cvt.u32.u64 %0, t; }" : "=r"(a) : "l"(p));
    return a;
}
__device__ __forceinline__ void ldm_x4(uint32_t* r, uint32_t addr) {
    asm volatile("ldmatrix.sync.aligned.m8n8.x4.shared.b16 {%0,%1,%2,%3}, [%4];"
                 : "=r"(r[0]), "=r"(r[1]), "=r"(r[2]), "=r"(r[3]) : "r"(addr));
}
__device__ __forceinline__ void mma_f16(float* c, const uint32_t* a,
                                        uint32_t b0, uint32_t b1) {
    asm volatile(
        "mma.sync.aligned.m16n8k16.row.col.f32.f16.f16.f32 "
        "{%0,%1,%2,%3}, {%4,%5,%6,%7}, {%8,%9}, {%0,%1,%2,%3};"
        : "+f"(c[0]), "+f"(c[1]), "+f"(c[2]), "+f"(c[3])
        : "r"(a[0]), "r"(a[1]), "r"(a[2]), "r"(a[3]), "r"(b0), "r"(b1));
}

// ---------------- kernel 1: sinusoidal PE -----------------------------------------
__global__ void k_pe() {
    int p = blockIdx.x;
    int i = threadIdx.x;  // 0..63
    double inv_rate = exp2(-(double)i * 0.20762050593046016);  // 10000^(-i/64)
    double ang = (double)p * inv_rate;
    double k = rint(ang * 0.15915494309189535);
    double r = fma(-k, 6.283185307179586, ang);
    r = fma(-k, 2.4492935982947064e-16, r);
    float s, c;
    sincosf((float)r, &s, &c);
    g_pe[p * NH + 2 * i]     = s;
    g_pe[p * NH + 2 * i + 1] = c;
}

// ---------------- kernel 2: xp = x + pe -------------------------------------------
__global__ void k_xp(const float* __restrict__ x) {
    int idx = blockIdx.x * blockDim.x + threadIdx.x;
    g_xp[idx] = x[idx] + g_pe[idx & (NS * NH - 1)];
}

// ---------------- kernel 3: wvf = Wv @ Wf -----------------------------------------
__global__ void k_wvf(const float* __restrict__ Wv, const float* __restrict__ Wf) {
    int h = threadIdx.x;
    float s = 0.f;
    #pragma unroll 8
    for (int d = 0; d < ND; d++) s += Wv[h * ND + d] * Wf[d];
    g_wvf[h] = s;
}

// ---------------- kernel 4: projections Q,K = xp@Wq, xp@Wk -> fp16 ----------------
__global__ __launch_bounds__(256, 2) void k_proj(const float* __restrict__ Wq,
                                                 const float* __restrict__ Wk) {
    extern __shared__ float sm[];
    float* As = sm;
    float* Bs = sm + 64 * 128;

    int t = threadIdx.x;
    int row0 = blockIdx.x * 64;

    const float4* Wq4 = (const float4*)Wq;
    const float4* Wk4 = (const float4*)Wk;
    float4* Bs4 = (float4*)Bs;
    #pragma unroll
    for (int i = 0; i < 16; i++) {
        int e = t + i * 256;
        int k = e >> 5, n4 = e & 31;
        Bs4[e] = (n4 < 16) ? Wq4[k * 16 + n4] : Wk4[k * 16 + (n4 - 16)];
    }
    const float4* xp4 = (const float4*)(g_xp + (size_t)row0 * NH);
    float4* As4 = (float4*)As;
    #pragma unroll
    for (int i = 0; i < 8; i++) As4[t + i * 256] = xp4[t + i * 256];
    __syncthreads();

    int tx = t & 31, ty = t >> 5;
    int n0 = tx * 4, m0 = ty * 8;

    u64 acc[8][2] = {};
    #pragma unroll 4
    for (int k = 0; k < 128; k++) {
        ulonglong2 b2 = *(const ulonglong2*)&Bs[k * 128 + n0];
        #pragma unroll
        for (int i = 0; i < 8; i++) {
            u64 a2 = pack_dup(As[(m0 + i) * 128 + k]);
            fma2(acc[i][0], a2, b2.x);
            fma2(acc[i][1], a2, b2.y);
        }
    }
    #pragma unroll
    for (int i = 0; i < 8; i++) {
        int m = row0 + m0 + i;
        float2 p0 = unpack2(acc[i][0]);
        float2 p1 = unpack2(acc[i][1]);
        __half2 hA = __floats2half2_rn(p0.x, p0.y);
        __half2 hB = __floats2half2_rn(p1.x, p1.y);
        uint2 v = make_uint2(*(uint32_t*)&hA, *(uint32_t*)&hB);
        if (tx < 16) ((uint2*)g_Qh)[m * 16 + tx] = v;
        else         ((uint2*)g_Kh)[m * 16 + (tx - 16)] = v;
    }
}

// ---------------- kernel 5: u = xp @ wvf ------------------------------------------
__global__ void k_u() {
    int w = (blockIdx.x * blockDim.x + threadIdx.x) >> 5;
    int lane = threadIdx.x & 31;
    const float* r = g_xp + (size_t)w * NH;
    float s = r[lane]      * g_wvf[lane]
            + r[lane + 32] * g_wvf[lane + 32]
            + r[lane + 64] * g_wvf[lane + 64]
            + r[lane + 96] * g_wvf[lane + 96];
    #pragma unroll
    for (int off = 16; off; off >>= 1) s += __shfl_down_sync(0xffffffffu, s, off);
    if (lane == 0) g_u[w] = s;
}

// ---------------- kernel 6: zero Z ------------------------------------------------
__global__ void k_zero() {
    g_Z[blockIdx.x * blockDim.x + threadIdx.x] = 0.f;
}

// ---------------- kernel 7: E = exp(QK^T/8)/16 via single-pass fp16 mma -----------
// 128x128 tile per CTA, 8 warps (4m x 2n), warp tile 32x64.
// Q,K already fp16 in GMEM; staging is a straight 16B copy.
// Epilogue: exp -> smem (XOR-swizzled, conflict-free) -> coalesced STG.128;
// in-kernel Z colsum via shfl + atomics.
__global__ __launch_bounds__(256, 2) void k_scores() {
    extern __shared__ __align__(16) __half smh[];
    const int PITCH = 72;
    __half* QH = smh;                     // [128][72]
    __half* KH = smh + 128 * PITCH;
    uint32_t* Esm = (uint32_t*)smh;       // epilogue reuse: [128][64] words (32KB)

    int t = threadIdx.x;
    int w = t >> 5, lane = t & 31;
    int b = blockIdx.z;
    int q0 = blockIdx.y * 128;
    int k0 = blockIdx.x * 128;

    // stage fp16 tiles (8 halves = 1 uint4 per load; 1024 uint4 per tile)
    const uint4* Qg = (const uint4*)(g_Qh + ((size_t)b * NS + q0) * ND);
    const uint4* Kg = (const uint4*)(g_Kh + ((size_t)b * NS + k0) * ND);
    #pragma unroll
    for (int i = 0; i < 4; i++) {
        int e = t + i * 256;          // uint4 index over [128 rows][8 octets]
        int r = e >> 3, c8 = e & 7;
        int off = r * PITCH + c8 * 8; // halves
        *(uint4*)(QH + off) = Qg[e];
        *(uint4*)(KH + off) = Kg[e];
    }
    __syncthreads();

    int warp_m = w & 3, warp_n = w >> 2;
    int m0 = warp_m * 32, n0 = warp_n * 64;
    int lr = lane & 15;                 // ldmatrix row within 16
    int lc = (lane >> 4) << 3;          // ldmatrix col half-block (0 or 8)

    uint32_t aQH = smem_u32(QH), aKH = smem_u32(KH);

    float acc[2][8][4] = {};

    #pragma unroll
    for (int ks = 0; ks < 4; ks++) {
        int col = ks * 16 + lc;
        uint32_t a0[4], a1[4];
        ldm_x4(a0, aQH + ((m0 + lr) * PITCH + col) * 2);
        ldm_x4(a1, aQH + ((m0 + 16 + lr) * PITCH + col) * 2);
        #pragma unroll
        for (int nb = 0; nb < 4; nb++) {
            uint32_t bk[4];
            ldm_x4(bk, aKH + ((n0 + nb * 16 + lr) * PITCH + col) * 2);
            mma_f16(acc[0][2 * nb],     a0, bk[0], bk[2]);
            mma_f16(acc[0][2 * nb + 1], a0, bk[1], bk[3]);
            mma_f16(acc[1][2 * nb],     a1, bk[0], bk[2]);
            mma_f16(acc[1][2 * nb + 1], a1, bk[1], bk[3]);
        }
    }

    __syncthreads();   // staging tiles dead; smem becomes E transpose buffer

    // epilogue part 1: exp/16 -> smem (XOR swizzle), accumulate column sums
    int g = lane >> 2, tq = lane & 3;
    float csum[16];
    #pragma unroll
    for (int j = 0; j < 16; j++) csum[j] = 0.f;

    #pragma unroll
    for (int mi = 0; mi < 2; mi++) {
        int rl = m0 + mi * 16 + g;             // local row (rl & 7 == g)
        uint32_t* erow = Esm + rl * 64;
        int sw = (g & 7) * 4;
        #pragma unroll
        for (int j = 0; j < 8; j++) {
            float e0 = __expf(acc[mi][j][0] * 0.125f) * 0.0625f;
            float e1 = __expf(acc[mi][j][1] * 0.125f) * 0.0625f;
            float e2 = __expf(acc[mi][j][2] * 0.125f) * 0.0625f;
            float e3 = __expf(acc[mi][j][3] * 0.125f) * 0.0625f;
            __half2 hA = __floats2half2_rn(e0, e1);
            __half2 hB = __floats2half2_rn(e2, e3);
            int c2a = (n0 >> 1) + 4 * j + tq;            // rows rl and rl+8
            erow[c2a ^ sw] = *(uint32_t*)&hA;
            (erow + 8 * 64)[c2a ^ sw] = *(uint32_t*)&hB;
            csum[2 * j]     += e0 + e2;
            csum[2 * j + 1] += e1 + e3;
        }
    }

    // column-sum reduce over g groups, then atomics
    #pragma unroll
    for (int off = 4; off <= 16; off <<= 1) {
        #pragma unroll
        for (int j = 0; j < 16; j++)
            csum[j] += __shfl_xor_sync(0xffffffffu, csum[j], off);
    }
    if (lane < 4) {
        float* zp = g_Z + b * NS + k0 + n0 + 2 * tq;
        #pragma unroll
        for (int j = 0; j < 8; j++) {
            atomicAdd(zp + j * 8,     csum[2 * j]);
            atomicAdd(zp + j * 8 + 1, csum[2 * j + 1]);
        }
    }
    __syncthreads();

    // epilogue part 2: coalesced stream-out. Half-warp per row: 16 lanes x 16B = 256B.
    {
        int hw = (t >> 4);          // 0..15: half-warp id
        int h = t & 15;             // 16B chunk within row
        #pragma unroll
        for (int it = 0; it < 8; it++) {
            int r = it * 16 + hw;   // local row 0..127
            uint32_t wbase = r * 64;
            int sw = (r & 7) * 4;
            uint32_t w0 = (4 * h) ^ sw;
            uint4 v = *(uint4*)&Esm[wbase + w0];
            __half* dst = g_Eh + ((size_t)b * NS + q0 + r) * NS + k0 + 8 * h;
            *(uint4*)dst = v;
        }
    }
}

// ---------------- kernel 8: w = u / Z ---------------------------------------------
__global__ void k_w() {
    int i = blockIdx.x * blockDim.x + threadIdx.x;
    g_w[i] = g_u[i] / g_Z[i];
}

// ---------------- kernel 9: out[b,q] = E[b,q,:] . w[b,:] + bf ---------------------
__global__ __launch_bounds__(256) void k_out(const float* __restrict__ bf,
                                             float* __restrict__ out) {
    __shared__ float red[256];
    int rq = blockIdx.x;
    int b = rq >> 11;
    int t = threadIdx.x;
    const uint2*  E2 = (const uint2*)(g_Eh + (size_t)rq * NS);
    const float4* w4 = (const float4*)(g_w + b * NS);
    float s = 0.f;
    #pragma unroll
    for (int i = 0; i < 2; i++) {
        int j = t + i * 256;
        uint2 e = E2[j];
        float2 f0 = __half22float2(*(__half2*)&e.x);
        float2 f1 = __half22float2(*(__half2*)&e.y);
        float4 w = w4[j];
        s += f0.x * w.x + f0.y * w.y + f1.x * w.z + f1.y * w.w;
    }
    red[t] = s;
    __syncthreads();
    #pragma unroll
    for (int off = 128; off > 0; off >>= 1) {
        if (t < off) red[t] += red[t + off];
        __syncthreads();
    }
    if (t == 0) out[rq] = red[0] + bf[0];
}

// ---------------- host launcher ---------------------------------------------------
extern "C" void kernel_launch(void* const* d_in, const int* in_sizes, int n_in,
                              void* d_out, int out_size) {
    (void)in_sizes; (void)n_in; (void)out_size;
    const float* x  = (const float*)d_in[0];
    const float* Wq = (const float*)d_in[1];
    const float* Wk = (const float*)d_in[2];
    const float* Wv = (const float*)d_in[3];
    const float* Wf = (const float*)d_in[4];
    const float* bf = (const float*)d_in[5];
    float* out = (float*)d_out;

    cudaFuncSetAttribute(k_proj,   cudaFuncAttributeMaxDynamicSharedMemorySize, 98304);
    cudaFuncSetAttribute(k_scores, cudaFuncAttributeMaxDynamicSharedMemorySize, 36864);

    k_pe<<<NS, 64>>>();
    k_xp<<<(NB * NS * NH) / 256, 256>>>(x);
    k_wvf<<<1, 128>>>(Wv, Wf);
    k_proj<<<(NB * NS) / 64, 256, 98304>>>(Wq, Wk);
    k_u<<<(NB * NS) / 8, 256>>>();
    k_zero<<<(NB * NS) / 256, 256>>>();
    dim3 sg(16, 16, 16);   // (k-tiles, q-tiles, batch)
    k_scores<<<sg, 256, 36864>>>();
    k_w<<<(NB * NS) / 256, 256>>>();
    k_out<<<NB * NS, 256>>>(bf, out);
}

// round 7
// speedup vs baseline: 2.4193x; 1.2473x over previous
#include <cuda_runtime.h>
#include <cuda_fp16.h>
#include <math.h>
#include <stdint.h>

#define NB 16
#define NS 2048
#define NH 128
#define ND 64

typedef unsigned long long u64;

// ---------------- scratch (device globals; no allocation allowed) ----------------
__device__ float g_pe[NS * NH];
__device__ __half g_Qh[NB * NS * ND];           // fp16 Q
__device__ __half g_Kh[NB * NS * ND];           // fp16 K
__device__ float g_wvf[NH];
__device__ float g_u[NB * NS];
__device__ float g_Z[NB * NS];
__device__ float g_w[NB * NS];
__device__ __half g_Eh[(size_t)NB * NS * NS];   // 134 MB: exp(scores)/16 in fp16

// ---------------- helpers ---------------------------------------------------------
__device__ __forceinline__ uint32_t smem_u32(const void* p) {
    uint32_t a;
    asm("{ .reg .u64 t; cvta.to.shared.u64 t, %1; cvt.u32.u64 %0, t; }" : "=r"(a) : "l"(p));
    return a;
}
__device__ __forceinline__ void ldm_x4(uint32_t* r, uint32_t addr) {
    asm volatile("ldmatrix.sync.aligned.m8n8.x4.shared.b16 {%0,%1,%2,%3}, [%4];"
                 : "=r"(r[0]), "=r"(r[1]), "=r"(r[2]), "=r"(r[3]) : "r"(addr));
}
__device__ __forceinline__ void mma_f16(float* c, const uint32_t* a,
                                        uint32_t b0, uint32_t b1) {
    asm volatile(
        "mma.sync.aligned.m16n8k16.row.col.f32.f16.f16.f32 "
        "{%0,%1,%2,%3}, {%4,%5,%6,%7}, {%8,%9}, {%0,%1,%2,%3};"
        : "+f"(c[0]), "+f"(c[1]), "+f"(c[2]), "+f"(c[3])
        : "r"(a[0]), "r"(a[1]), "r"(a[2]), "r"(a[3]), "r"(b0), "r"(b1));
}
__device__ __forceinline__ float ex2f(float v) {
    float r; asm("ex2.approx.ftz.f32 %0, %1;" : "=f"(r) : "f"(v)); return r;
}

// ---------------- kernel 1: sinusoidal PE -----------------------------------------
__global__ void k_pe() {
    int p = blockIdx.x;
    int i = threadIdx.x;  // 0..63
    double inv_rate = exp2(-(double)i * 0.20762050593046016);  // 10000^(-i/64)
    double ang = (double)p * inv_rate;
    double k = rint(ang * 0.15915494309189535);
    double r = fma(-k, 6.283185307179586, ang);
    r = fma(-k, 2.4492935982947064e-16, r);
    float s, c;
    sincosf((float)r, &s, &c);
    g_pe[p * NH + 2 * i]     = s;
    g_pe[p * NH + 2 * i + 1] = c;
}

// ---------------- kernel 2: wvf = Wv @ Wf -----------------------------------------
__global__ void k_wvf(const float* __restrict__ Wv, const float* __restrict__ Wf) {
    int h = threadIdx.x;
    float s = 0.f;
    #pragma unroll 8
    for (int d = 0; d < ND; d++) s += Wv[h * ND + d] * Wf[d];
    g_wvf[h] = s;
}

// ---------------- kernel 3: fused xp=x+pe -> {Q,K} fp16 (HMMA) + u ----------------
// 128 rows x (64 Q | 64 K cols) x depth 128 per CTA, 512 threads.
// smem tiles: 256B rows, 16B-chunk XOR swizzle -> conflict-free STS + ldmatrix.
// u[row] = fp32 xp . wvf computed during staging (exact path, shfl reduce).
__global__ __launch_bounds__(512, 2) void k_qk(const float* __restrict__ x,
                                               const float* __restrict__ Wq,
                                               const float* __restrict__ Wk) {
    extern __shared__ __align__(16) char qs[];
    char* XPs = qs;             // [128 rows][256 B]
    char* Ws  = qs + 32768;     // [128 n][256 B]
    int t = threadIdx.x;
    int w = t >> 5, lane = t & 31;
    int r0 = blockIdx.x * 128;
    int s0 = r0 & (NS - 1);

    // stage W transposed to [n][k] fp16: task id -> (n, k-octet o)
    #pragma unroll
    for (int i = 0; i < 4; i++) {
        int id = t + i * 512;
        int n = id & 127, o = id >> 7;
        const float* src = (n < 64) ? (Wq + n) : (Wk + (n - 64));
        float v0 = src[(8 * o + 0) * 64], v1 = src[(8 * o + 1) * 64];
        float v2 = src[(8 * o + 2) * 64], v3 = src[(8 * o + 3) * 64];
        float v4 = src[(8 * o + 4) * 64], v5 = src[(8 * o + 5) * 64];
        float v6 = src[(8 * o + 6) * 64], v7 = src[(8 * o + 7) * 64];
        __half2 h0 = __floats2half2_rn(v0, v1);
        __half2 h1 = __floats2half2_rn(v2, v3);
        __half2 h2 = __floats2half2_rn(v4, v5);
        __half2 h3 = __floats2half2_rn(v6, v7);
        int chunk = o ^ (n & 7);
        *(uint4*)(Ws + n * 256 + chunk * 16) =
            make_uint4(*(uint32_t*)&h0, *(uint32_t*)&h1, *(uint32_t*)&h2, *(uint32_t*)&h3);
    }

    // stage XP (fp16) + u (fp32): warp w handles rows w+16i, lane = quad
    float4 wv = ((const float4*)g_wvf)[lane];
    #pragma unroll
    for (int i = 0; i < 8; i++) {
        int row = w + 16 * i;
        float4 xv = ((const float4*)(x    + (size_t)(r0 + row) * NH))[lane];
        float4 pv = ((const float4*)(g_pe + (size_t)(s0 + row) * NH))[lane];
        float xpx = xv.x + pv.x, xpy = xv.y + pv.y;
        float xpz = xv.z + pv.z, xpw = xv.w + pv.w;
        float up = xpx * wv.x + xpy * wv.y + xpz * wv.z + xpw * wv.w;
        #pragma unroll
        for (int off = 16; off; off >>= 1) up += __shfl_down_sync(0xffffffffu, up, off);
        if (lane == 0) g_u[r0 + row] = up;
        __half2 hA = __floats2half2_rn(xpx, xpy);
        __half2 hB = __floats2half2_rn(xpz, xpw);
        int chunk = (lane >> 1) ^ (row & 7);
        *(uint2*)(XPs + row * 256 + chunk * 16 + (lane & 1) * 8) =
            make_uint2(*(uint32_t*)&hA, *(uint32_t*)&hB);
    }
    __syncthreads();

    // mma: 16 warps = 8 warp_m x 2 warp_n; warp tile 16 rows x 64 cols
    int warp_m = w >> 1, warp_n = w & 1;
    int m0 = warp_m * 16, nb0 = warp_n * 64;
    int lr = lane & 15, lch = lane >> 4;   // col 8-half block 0/1

    uint32_t aXP = smem_u32(XPs), aW = smem_u32(Ws);
    float acc[8][4] = {};
    #pragma unroll
    for (int ks = 0; ks < 8; ks++) {
        uint32_t a[4];
        int rowA = m0 + lr;
        ldm_x4(a, aXP + rowA * 256 + (((2 * ks + lch) ^ (rowA & 7)) << 4));
        #pragma unroll
        for (int nb = 0; nb < 4; nb++) {
            int rowB = nb0 + nb * 16 + lr;
            uint32_t bk[4];
            ldm_x4(bk, aW + rowB * 256 + (((2 * ks + lch) ^ (rowB & 7)) << 4));
            mma_f16(acc[2 * nb],     a, bk[0], bk[2]);
            mma_f16(acc[2 * nb + 1], a, bk[1], bk[3]);
        }
    }

    // store Q or K (warp_n selects), fp16 half2 per fragment pair
    int g = lane >> 2, tq = lane & 3;
    __half* base = warp_n ? g_Kh : g_Qh;
    #pragma unroll
    for (int mi = 0; mi < 2; mi++) {
        __half* drow = base + (size_t)(r0 + m0 + 8 * mi + g) * ND;
        #pragma unroll
        for (int nb = 0; nb < 4; nb++) {
            #pragma unroll
            for (int jj = 0; jj < 2; jj++) {
                int col = nb * 16 + jj * 8 + 2 * tq;
                __half2 hv = __floats2half2_rn(acc[2 * nb + jj][2 * mi],
                                               acc[2 * nb + jj][2 * mi + 1]);
                *(uint32_t*)(drow + col) = *(uint32_t*)&hv;
            }
        }
    }
}

// ---------------- kernel 4: zero Z ------------------------------------------------
__global__ void k_zero() {
    g_Z[blockIdx.x * blockDim.x + threadIdx.x] = 0.f;
}

// ---------------- kernel 5: E = exp(QK^T/8)/16 via single-pass fp16 mma -----------
__global__ __launch_bounds__(256, 2) void k_scores() {
    extern __shared__ __align__(16) __half smh[];
    const int PITCH = 72;
    __half* QH = smh;                     // [128][72]
    __half* KH = smh + 128 * PITCH;
    uint32_t* Esm = (uint32_t*)smh;       // epilogue reuse: [128][64] words (32KB)

    int t = threadIdx.x;
    int w = t >> 5, lane = t & 31;
    int b = blockIdx.z;
    int q0 = blockIdx.y * 128;
    int k0 = blockIdx.x * 128;

    const uint4* Qg = (const uint4*)(g_Qh + ((size_t)b * NS + q0) * ND);
    const uint4* Kg = (const uint4*)(g_Kh + ((size_t)b * NS + k0) * ND);
    #pragma unroll
    for (int i = 0; i < 4; i++) {
        int e = t + i * 256;          // uint4 index over [128 rows][8 octets]
        int r = e >> 3, c8 = e & 7;
        int off = r * PITCH + c8 * 8;
        *(uint4*)(QH + off) = Qg[e];
        *(uint4*)(KH + off) = Kg[e];
    }
    __syncthreads();

    int warp_m = w & 3, warp_n = w >> 2;
    int m0 = warp_m * 32, n0 = warp_n * 64;
    int lr = lane & 15;
    int lc = (lane >> 4) << 3;

    uint32_t aQH = smem_u32(QH), aKH = smem_u32(KH);
    float acc[2][8][4] = {};

    #pragma unroll
    for (int ks = 0; ks < 4; ks++) {
        int col = ks * 16 + lc;
        uint32_t a0[4], a1[4];
        ldm_x4(a0, aQH + ((m0 + lr) * PITCH + col) * 2);
        ldm_x4(a1, aQH + ((m0 + 16 + lr) * PITCH + col) * 2);
        #pragma unroll
        for (int nb = 0; nb < 4; nb++) {
            uint32_t bk[4];
            ldm_x4(bk, aKH + ((n0 + nb * 16 + lr) * PITCH + col) * 2);
            mma_f16(acc[0][2 * nb],     a0, bk[0], bk[2]);
            mma_f16(acc[0][2 * nb + 1], a0, bk[1], bk[3]);
            mma_f16(acc[1][2 * nb],     a1, bk[0], bk[2]);
            mma_f16(acc[1][2 * nb + 1], a1, bk[1], bk[3]);
        }
    }

    __syncthreads();   // staging tiles dead; smem becomes E transpose buffer

    // epilogue part 1: E = ex2(s*0.18033688 - 4) -> smem (XOR swizzle), colsums
    const float C = 0.18033688f;
    int g = lane >> 2, tq = lane & 3;
    float csum[16];
    #pragma unroll
    for (int j = 0; j < 16; j++) csum[j] = 0.f;

    #pragma unroll
    for (int mi = 0; mi < 2; mi++) {
        int rl = m0 + mi * 16 + g;
        uint32_t* erow = Esm + rl * 64;
        int sw = (g & 7) * 4;
        #pragma unroll
        for (int j = 0; j < 8; j++) {
            float e0 = ex2f(fmaf(acc[mi][j][0], C, -4.0f));
            float e1 = ex2f(fmaf(acc[mi][j][1], C, -4.0f));
            float e2 = ex2f(fmaf(acc[mi][j][2], C, -4.0f));
            float e3 = ex2f(fmaf(acc[mi][j][3], C, -4.0f));
            __half2 hA = __floats2half2_rn(e0, e1);
            __half2 hB = __floats2half2_rn(e2, e3);
            int c2a = (n0 >> 1) + 4 * j + tq;
            erow[c2a ^ sw] = *(uint32_t*)&hA;
            (erow + 8 * 64)[c2a ^ sw] = *(uint32_t*)&hB;
            csum[2 * j]     += e0 + e2;
            csum[2 * j + 1] += e1 + e3;
        }
    }

    #pragma unroll
    for (int off = 4; off <= 16; off <<= 1) {
        #pragma unroll
        for (int j = 0; j < 16; j++)
            csum[j] += __shfl_xor_sync(0xffffffffu, csum[j], off);
    }
    if (lane < 4) {
        float* zp = g_Z + b * NS + k0 + n0 + 2 * tq;
        #pragma unroll
        for (int j = 0; j < 8; j++) {
            atomicAdd(zp + j * 8,     csum[2 * j]);
            atomicAdd(zp + j * 8 + 1, csum[2 * j + 1]);
        }
    }
    __syncthreads();

    // epilogue part 2: coalesced stream-out, half-warp per row (256B)
    {
        int hw = t >> 4;
        int h = t & 15;
        #pragma unroll
        for (int it = 0; it < 8; it++) {
            int r = it * 16 + hw;
            uint32_t wbase = r * 64;
            int sw = (r & 7) * 4;
            uint4 v = *(uint4*)&Esm[wbase + ((4 * h) ^ sw)];
            __half* dst = g_Eh + ((size_t)b * NS + q0 + r) * NS + k0 + 8 * h;
            *(uint4*)dst = v;
        }
    }
}

// ---------------- kernel 6: w = u / Z ---------------------------------------------
__global__ void k_w() {
    int i = blockIdx.x * blockDim.x + threadIdx.x;
    g_w[i] = g_u[i] / g_Z[i];
}

// ---------------- kernel 7: out[b,q] = E[b,q,:] . w[b,:] + bf ---------------------
__global__ __launch_bounds__(256) void k_out(const float* __restrict__ bf,
                                             float* __restrict__ out) {
    __shared__ float red[256];
    int rq = blockIdx.x;
    int b = rq >> 11;
    int t = threadIdx.x;
    const uint2*  E2 = (const uint2*)(g_Eh + (size_t)rq * NS);
    const float4* w4 = (const float4*)(g_w + b * NS);
    float s = 0.f;
    #pragma unroll
    for (int i = 0; i < 2; i++) {
        int j = t + i * 256;
        uint2 e = E2[j];
        float2 f0 = __half22float2(*(__half2*)&e.x);
        float2 f1 = __half22float2(*(__half2*)&e.y);
        float4 w = w4[j];
        s += f0.x * w.x + f0.y * w.y + f1.x * w.z + f1.y * w.w;
    }
    red[t] = s;
    __syncthreads();
    #pragma unroll
    for (int off = 128; off > 0; off >>= 1) {
        if (t < off) red[t] += red[t + off];
        __syncthreads();
    }
    if (t == 0) out[rq] = red[0] + bf[0];
}

// ---------------- host launcher ---------------------------------------------------
extern "C" void kernel_launch(void* const* d_in, const int* in_sizes, int n_in,
                              void* d_out, int out_size) {
    (void)in_sizes; (void)n_in; (void)out_size;
    const float* x  = (const float*)d_in[0];
    const float* Wq = (const float*)d_in[1];
    const float* Wk = (const float*)d_in[2];
    const float* Wv = (const float*)d_in[3];
    const float* Wf = (const float*)d_in[4];
    const float* bf = (const float*)d_in[5];
    float* out = (float*)d_out;

    cudaFuncSetAttribute(k_qk,     cudaFuncAttributeMaxDynamicSharedMemorySize, 65536);
    cudaFuncSetAttribute(k_scores, cudaFuncAttributeMaxDynamicSharedMemorySize, 36864);

    k_pe<<<NS, 64>>>();
    k_wvf<<<1, 128>>>(Wv, Wf);
    k_qk<<<(NB * NS) / 128, 512, 65536>>>(x, Wq, Wk);
    k_zero<<<(NB * NS) / 256, 256>>>();
    dim3 sg(16, 16, 16);   // (k-tiles, q-tiles, batch)
    k_scores<<<sg, 256, 36864>>>();
    k_w<<<(NB * NS) / 256, 256>>>();
    k_out<<<NB * NS, 256>>>(bf, out);
}